// round 1
// baseline (speedup 1.0000x reference)
#include <cuda_runtime.h>

#define N_ATOMS 200000
#define IN_F    256
#define OUT_F   256
#define BOND_F  6
#define GROW    264          // gathered row: 256 atom-sum + 6 bond-sum + 2 pad
#define KTOT    520          // 256 (self) + 264 (gathered, padded)
#define EPSV    1e-5f

// ---------------- device scratch (static: no allocations allowed) ------------
__device__ float g_G[(size_t)N_ATOMS * GROW];        // ~211 MB gathered features
__device__ float g_W[5 * KTOT * OUT_F];              // concatenated padded weights
__device__ float g_sum[OUT_F];
__device__ float g_sumsq[OUT_F];
__device__ float g_scale[OUT_F];
__device__ float g_shift[OUT_F];

// ---------------- f32x2 packed math helpers ---------------------------------
__device__ __forceinline__ unsigned long long pk2(float lo, float hi) {
    unsigned long long r;
    asm("mov.b64 %0, {%1, %2};" : "=l"(r) : "f"(lo), "f"(hi));
    return r;
}
__device__ __forceinline__ void fma2(unsigned long long &d, unsigned long long a,
                                     unsigned long long b) {
    asm("fma.rn.f32x2 %0, %1, %2, %0;" : "+l"(d) : "l"(a), "l"(b));
}
__device__ __forceinline__ void upk2(unsigned long long v, float &lo, float &hi) {
    asm("mov.b64 {%0, %1}, %2;" : "=f"(lo), "=f"(hi) : "l"(v));
}

// ---------------- kernel 1: build padded weights, zero BN accumulators ------
__global__ void prep_kernel(const float* __restrict__ Wself,
                            const float* __restrict__ W1, const float* __restrict__ W2,
                            const float* __restrict__ W3, const float* __restrict__ W4,
                            const float* __restrict__ W5) {
    int tid = blockIdx.x * blockDim.x + threadIdx.x;
    if (tid < OUT_F) { g_sum[tid] = 0.f; g_sumsq[tid] = 0.f; }
    const int total = 5 * KTOT * OUT_F;
    for (int i = tid; i < total; i += gridDim.x * blockDim.x) {
        int d   = i / (KTOT * OUT_F);
        int rem = i - d * (KTOT * OUT_F);
        int r   = rem >> 8;
        int c   = rem & 255;
        float v;
        if (r < IN_F) {
            v = Wself[r * OUT_F + c];
        } else if (r < IN_F + 262) {
            const float* Wd = (d == 0) ? W1 : (d == 1) ? W2 : (d == 2) ? W3
                            : (d == 3) ? W4 : W5;
            v = Wd[(r - IN_F) * OUT_F + c];
        } else {
            v = 0.f;   // pad rows 518,519
        }
        g_W[i] = v;
    }
}

// ---------------- kernel 2: gather + neighbor sum (one warp per atom) -------
__global__ void gather_kernel(const float* __restrict__ A, const float* __restrict__ B,
    const int* __restrict__ an1, const int* __restrict__ an2, const int* __restrict__ an3,
    const int* __restrict__ an4, const int* __restrict__ an5,
    const int* __restrict__ bn1, const int* __restrict__ bn2, const int* __restrict__ bn3,
    const int* __restrict__ bn4, const int* __restrict__ bn5) {
    int w    = (blockIdx.x * blockDim.x + threadIdx.x) >> 5;
    int lane = threadIdx.x & 31;
    if (w >= N_ATOMS) return;
    int deg, li; const int *an, *bnp;
    if      (w <  20000) { deg = 1; li = w;           an = an1; bnp = bn1; }
    else if (w <  80000) { deg = 2; li = w -  20000;  an = an2; bnp = bn2; }
    else if (w < 140000) { deg = 3; li = w -  80000;  an = an3; bnp = bn3; }
    else if (w < 180000) { deg = 4; li = w - 140000;  an = an4; bnp = bn4; }
    else                 { deg = 5; li = w - 180000;  an = an5; bnp = bn5; }

    float4 a0 = {0.f,0.f,0.f,0.f}, a1 = {0.f,0.f,0.f,0.f};
    float bacc = 0.f;
    for (int j = 0; j < deg; j++) {
        int ai = an[li * deg + j];
        const float4* src = (const float4*)(A + (size_t)ai * IN_F);
        float4 s0 = src[lane];
        float4 s1 = src[lane + 32];
        a0.x += s0.x; a0.y += s0.y; a0.z += s0.z; a0.w += s0.w;
        a1.x += s1.x; a1.y += s1.y; a1.z += s1.z; a1.w += s1.w;
        if (lane < BOND_F) {
            int bi = bnp[li * deg + j];
            bacc += B[(size_t)bi * BOND_F + lane];
        }
    }
    float4* dst = (float4*)(g_G + (size_t)w * GROW);
    dst[lane]      = a0;
    dst[lane + 32] = a1;
    if (lane < 8)
        g_G[(size_t)w * GROW + IN_F + lane] = (lane < BOND_F) ? bacc : 0.f;
}

// ---------------- kernel 3: fused GEMM + bias + ReLU -------------------------
// M-tile 32 (all segment boundaries are multiples of 32 -> no straddle),
// N = 256 full, K = 520 in 8-wide tiles. 128 threads, 8x8 outputs/thread,
// f32x2 packed FMAs (2x FFMA throughput vs 3-reg FFMA on sm_103a).
__global__ void __launch_bounds__(128) gemm_kernel(const float* __restrict__ A,
                                                   const float* __restrict__ bias,
                                                   float* __restrict__ out) {
    __shared__ float Xs[8][36];        // [kk][row], pad 36 -> conflict-free
    __shared__ float Ws[8 * 256];      // [kk][col]

    int t  = threadIdx.x;
    int tx = t & 31, ty = t >> 5;
    int row0 = blockIdx.x * 32;
    int seg  = (row0 <  20000) ? 0 : (row0 <  80000) ? 1 : (row0 < 140000) ? 2
             : (row0 < 180000) ? 3 : 4;
    const float* W = g_W + (size_t)seg * KTOT * OUT_F;

    unsigned long long acc[8][4];
    const unsigned long long z = pk2(0.f, 0.f);
#pragma unroll
    for (int r = 0; r < 8; r++)
#pragma unroll
        for (int p = 0; p < 4; p++) acc[r][p] = z;

    int r_a  = t >> 3;   // 0..15
    int kk_a = t & 7;

    for (int kt = 0; kt < KTOT / 8; kt++) {
        int k0 = kt * 8;
        // stage gmem loads into registers (overlap with previous compute)
        float xv0, xv1;
        if (k0 < IN_F) {
            xv0 = A[(size_t)(row0 + r_a)      * IN_F + k0 + kk_a];
            xv1 = A[(size_t)(row0 + r_a + 16) * IN_F + k0 + kk_a];
        } else {
            xv0 = g_G[(size_t)(row0 + r_a)      * GROW + (k0 - IN_F) + kk_a];
            xv1 = g_G[(size_t)(row0 + r_a + 16) * GROW + (k0 - IN_F) + kk_a];
        }
        const float4* wsrc = (const float4*)(W + (size_t)k0 * OUT_F);
        float4 wv0 = wsrc[t], wv1 = wsrc[t + 128], wv2 = wsrc[t + 256], wv3 = wsrc[t + 384];

        __syncthreads();
        Xs[kk_a][r_a]      = xv0;
        Xs[kk_a][r_a + 16] = xv1;
        float4* wdst = (float4*)Ws;
        wdst[t] = wv0; wdst[t + 128] = wv1; wdst[t + 256] = wv2; wdst[t + 384] = wv3;
        __syncthreads();

#pragma unroll
        for (int kk = 0; kk < 8; kk++) {
            float4 xa = *(const float4*)&Xs[kk][ty * 8];
            float4 xb = *(const float4*)&Xs[kk][ty * 8 + 4];
            const float4* w4 = (const float4*)&Ws[kk * 256];
            float4 w0 = w4[tx], w1 = w4[32 + tx];
            unsigned long long wp0 = pk2(w0.x, w0.y), wp1 = pk2(w0.z, w0.w);
            unsigned long long wp2 = pk2(w1.x, w1.y), wp3 = pk2(w1.z, w1.w);
            float xr[8] = {xa.x, xa.y, xa.z, xa.w, xb.x, xb.y, xb.z, xb.w};
#pragma unroll
            for (int r = 0; r < 8; r++) {
                unsigned long long xp = pk2(xr[r], xr[r]);
                fma2(acc[r][0], xp, wp0);
                fma2(acc[r][1], xp, wp1);
                fma2(acc[r][2], xp, wp2);
                fma2(acc[r][3], xp, wp3);
            }
        }
    }

    const float4* b4 = (const float4*)bias;
    float4 bb0 = b4[tx], bb1 = b4[32 + tx];
#pragma unroll
    for (int r = 0; r < 8; r++) {
        int grow = row0 + ty * 8 + r;
        float o[8];
        upk2(acc[r][0], o[0], o[1]); upk2(acc[r][1], o[2], o[3]);
        upk2(acc[r][2], o[4], o[5]); upk2(acc[r][3], o[6], o[7]);
        float4 v0, v1;
        v0.x = fmaxf(o[0] + bb0.x, 0.f); v0.y = fmaxf(o[1] + bb0.y, 0.f);
        v0.z = fmaxf(o[2] + bb0.z, 0.f); v0.w = fmaxf(o[3] + bb0.w, 0.f);
        v1.x = fmaxf(o[4] + bb1.x, 0.f); v1.y = fmaxf(o[5] + bb1.y, 0.f);
        v1.z = fmaxf(o[6] + bb1.z, 0.f); v1.w = fmaxf(o[7] + bb1.w, 0.f);
        *(float4*)(out + (size_t)grow * OUT_F + 4 * tx)        = v0;
        *(float4*)(out + (size_t)grow * OUT_F + 128 + 4 * tx)  = v1;
    }
}

// ---------------- kernel 4: BN column stats ----------------------------------
__global__ void bn_stats_kernel(const float* __restrict__ out) {
    int c    = threadIdx.x;                  // 256 threads = 256 columns
    int rows = N_ATOMS / gridDim.x;
    int r0   = blockIdx.x * rows;
    float s = 0.f, q = 0.f;
    for (int r = r0; r < r0 + rows; r++) {
        float v = out[(size_t)r * OUT_F + c];
        s += v; q += v * v;
    }
    atomicAdd(&g_sum[c], s);
    atomicAdd(&g_sumsq[c], q);
}

// ---------------- kernel 5: BN finalize (scale/shift per column) -------------
__global__ void bn_finalize_kernel(const float* __restrict__ bnw,
                                   const float* __restrict__ bnb) {
    int c = threadIdx.x;
    float mean = g_sum[c]   * (1.f / N_ATOMS);
    float var  = g_sumsq[c] * (1.f / N_ATOMS) - mean * mean;
    float sc   = bnw[c] / sqrtf(var + EPSV);
    g_scale[c] = sc;
    g_shift[c] = bnb[c] - mean * sc;
}

// ---------------- kernel 6: BN apply (vectorized, in place) ------------------
__global__ void bn_apply_kernel(float* __restrict__ out) {
    const int total4 = N_ATOMS * (OUT_F / 4);
    for (int i = blockIdx.x * blockDim.x + threadIdx.x; i < total4;
         i += gridDim.x * blockDim.x) {
        int c4 = i & 63;
        float4 v  = ((float4*)out)[i];
        float4 sc = ((const float4*)g_scale)[c4];
        float4 sh = ((const float4*)g_shift)[c4];
        v.x = v.x * sc.x + sh.x;
        v.y = v.y * sc.y + sh.y;
        v.z = v.z * sc.z + sh.z;
        v.w = v.w * sc.w + sh.w;
        ((float4*)out)[i] = v;
    }
}

// ---------------- launcher ---------------------------------------------------
extern "C" void kernel_launch(void* const* d_in, const int* in_sizes, int n_in,
                              void* d_out, int out_size) {
    const float* A = (const float*)d_in[0];
    const float* B = (const float*)d_in[1];
    const int *an[5], *bnp[5];
    // setup_inputs dict order interleaves (atom_nbrs_d, bond_nbrs_d); the
    // reference signature groups them. Disambiguate via in_sizes[3]:
    //   interleaved: idx3 = bond_nbrs_1 (20000 elems)
    //   grouped:     idx3 = atom_nbrs_2 (120000 elems)
    if (in_sizes[3] == 20000) {
        for (int d = 0; d < 5; d++) {
            an[d]  = (const int*)d_in[2 + 2 * d];
            bnp[d] = (const int*)d_in[3 + 2 * d];
        }
    } else {
        for (int d = 0; d < 5; d++) {
            an[d]  = (const int*)d_in[2 + d];
            bnp[d] = (const int*)d_in[7 + d];
        }
    }
    const float* Wself = (const float*)d_in[12];
    const float* bias  = (const float*)d_in[13];
    const float* Wd[5];
    for (int d = 0; d < 5; d++) Wd[d] = (const float*)d_in[14 + d];
    const float* bnw = (const float*)d_in[19];
    const float* bnb = (const float*)d_in[20];
    float* out = (float*)d_out;

    prep_kernel<<<256, 256>>>(Wself, Wd[0], Wd[1], Wd[2], Wd[3], Wd[4]);
    gather_kernel<<<N_ATOMS / 8, 256>>>(A, B,
        an[0], an[1], an[2], an[3], an[4],
        bnp[0], bnp[1], bnp[2], bnp[3], bnp[4]);
    gemm_kernel<<<N_ATOMS / 32, 128>>>(A, bias, out);
    bn_stats_kernel<<<500, 256>>>(out);
    bn_finalize_kernel<<<1, 256>>>(bnw, bnb);
    bn_apply_kernel<<<2048, 256>>>(out);
}

// round 6
// speedup vs baseline: 1.0977x; 1.0977x over previous
#include <cuda_runtime.h>
#include <cuda_bf16.h>
#include <cstdint>

#define N_ATOMS 200000
#define IN_F    256
#define OUT_F   256
#define BOND_F  6
#define GROW    264          // gathered row: 256 atom-sum + 6 bond-sum + 2 pad
#define KPAD    544          // 520 padded to 17*32
#define KCH     32           // K per chunk
#define NCHUNK  17
#define TILE_M  128
#define TILE_N  128
#define EPSV    1e-5f

#define ROWB    80           // smem bytes per row (64B data + 16B pad, conflict-free)

// ---------------- device scratch (static: no allocations allowed) ------------
__device__ float g_G[(size_t)N_ATOMS * GROW];        // gathered features
__device__ float g_Wt[5 * OUT_F * KPAD];             // K-major padded weights [seg][n][k]
__device__ float g_sum[OUT_F];
__device__ float g_sumsq[OUT_F];
__device__ float g_scale[OUT_F];
__device__ float g_shift[OUT_F];

// ---------------- helpers ----------------------------------------------------
__device__ __forceinline__ uint32_t s2u(const void* p) {
    uint32_t a;
    asm("{ .reg .u64 t; cvta.to.shared.u64 t, %1; cvt.u32.u64 %0, t; }"
        : "=r"(a) : "l"(p));
    return a;
}
__device__ __forceinline__ void sts128(uint32_t addr, uint32_t a, uint32_t b,
                                       uint32_t c, uint32_t d) {
    asm volatile("st.shared.v4.b32 [%0], {%1, %2, %3, %4};"
                 :: "r"(addr), "r"(a), "r"(b), "r"(c), "r"(d) : "memory");
}
__device__ __forceinline__ void ldmx4(uint32_t* r, uint32_t addr) {
    asm volatile("ldmatrix.sync.aligned.m8n8.x4.shared.b16 {%0,%1,%2,%3}, [%4];"
                 : "=r"(r[0]), "=r"(r[1]), "=r"(r[2]), "=r"(r[3]) : "r"(addr));
}
// B operand: W stored [n][k] row-major == B^T, so NON-trans ldmatrix yields the
// col-major B fragment directly (reg packs consecutive k for fixed n).
__device__ __forceinline__ void ldmx2(uint32_t* r, uint32_t addr) {
    asm volatile("ldmatrix.sync.aligned.m8n8.x2.shared.b16 {%0,%1}, [%2];"
                 : "=r"(r[0]), "=r"(r[1]) : "r"(addr));
}
__device__ __forceinline__ void mma_bf16(float* c, const uint32_t* a, const uint32_t* b) {
    asm volatile(
        "mma.sync.aligned.m16n8k16.row.col.f32.bf16.bf16.f32 "
        "{%0,%1,%2,%3}, {%4,%5,%6,%7}, {%8,%9}, {%0,%1,%2,%3};"
        : "+f"(c[0]), "+f"(c[1]), "+f"(c[2]), "+f"(c[3])
        : "r"(a[0]), "r"(a[1]), "r"(a[2]), "r"(a[3]), "r"(b[0]), "r"(b[1]));
}
// split x into bf16 hi + bf16 lo, return packed pair-words
__device__ __forceinline__ void split2(float x, float y, uint32_t& h, uint32_t& l) {
    __nv_bfloat16 hx = __float2bfloat16(x);
    __nv_bfloat16 hy = __float2bfloat16(y);
    float rx = x - __bfloat162float(hx);
    float ry = y - __bfloat162float(hy);
    __nv_bfloat16 lx = __float2bfloat16(rx);
    __nv_bfloat16 ly = __float2bfloat16(ry);
    h = ((uint32_t)__bfloat16_as_ushort(hy) << 16) | __bfloat16_as_ushort(hx);
    l = ((uint32_t)__bfloat16_as_ushort(ly) << 16) | __bfloat16_as_ushort(lx);
}

// ---------------- kernel 1: transpose+pad weights, zero BN accumulators ------
__global__ void prep_kernel(const float* __restrict__ Wself,
                            const float* __restrict__ W1, const float* __restrict__ W2,
                            const float* __restrict__ W3, const float* __restrict__ W4,
                            const float* __restrict__ W5) {
    int tid = blockIdx.x * blockDim.x + threadIdx.x;
    if (tid < OUT_F) { g_sum[tid] = 0.f; g_sumsq[tid] = 0.f; }
    const int total = 5 * OUT_F * KPAD;
    for (int i = tid; i < total; i += gridDim.x * blockDim.x) {
        int seg = i / (OUT_F * KPAD);
        int rem = i - seg * (OUT_F * KPAD);
        int n   = rem / KPAD;
        int k   = rem - n * KPAD;
        float v = 0.f;
        if (k < IN_F) {
            v = Wself[k * OUT_F + n];
        } else if (k < IN_F + 262) {
            const float* Wd = (seg == 0) ? W1 : (seg == 1) ? W2 : (seg == 2) ? W3
                            : (seg == 3) ? W4 : W5;
            v = Wd[(k - IN_F) * OUT_F + n];
        }
        g_Wt[i] = v;
    }
}

// ---------------- kernel 2: gather + neighbor sum (one warp per atom) -------
__global__ void gather_kernel(const float* __restrict__ A, const float* __restrict__ B,
    const int* __restrict__ an1, const int* __restrict__ an2, const int* __restrict__ an3,
    const int* __restrict__ an4, const int* __restrict__ an5,
    const int* __restrict__ bn1, const int* __restrict__ bn2, const int* __restrict__ bn3,
    const int* __restrict__ bn4, const int* __restrict__ bn5) {
    int w    = (blockIdx.x * blockDim.x + threadIdx.x) >> 5;
    int lane = threadIdx.x & 31;
    if (w >= N_ATOMS) return;
    int deg, li; const int *an, *bnp;
    if      (w <  20000) { deg = 1; li = w;           an = an1; bnp = bn1; }
    else if (w <  80000) { deg = 2; li = w -  20000;  an = an2; bnp = bn2; }
    else if (w < 140000) { deg = 3; li = w -  80000;  an = an3; bnp = bn3; }
    else if (w < 180000) { deg = 4; li = w - 140000;  an = an4; bnp = bn4; }
    else                 { deg = 5; li = w - 180000;  an = an5; bnp = bn5; }

    float4 a0 = {0.f,0.f,0.f,0.f}, a1 = {0.f,0.f,0.f,0.f};
    float bacc = 0.f;
    for (int j = 0; j < deg; j++) {
        int ai = an[li * deg + j];
        const float4* src = (const float4*)(A + (size_t)ai * IN_F);
        float4 s0 = src[lane];
        float4 s1 = src[lane + 32];
        a0.x += s0.x; a0.y += s0.y; a0.z += s0.z; a0.w += s0.w;
        a1.x += s1.x; a1.y += s1.y; a1.z += s1.z; a1.w += s1.w;
        if (lane < BOND_F) {
            int bi = bnp[li * deg + j];
            bacc += B[(size_t)bi * BOND_F + lane];
        }
    }
    float4* dst = (float4*)(g_G + (size_t)w * GROW);
    dst[lane]      = a0;
    dst[lane + 32] = a1;
    if (lane < 8)
        g_G[(size_t)w * GROW + IN_F + lane] = (lane < BOND_F) ? bacc : 0.f;
}

// ---------------- kernel 3: bf16x3 mma.sync GEMM + bias + ReLU + BN stats ----
// CTA 256 thr = 8 warps (2 M x 4 N), tile 128x128, K=544 in 17 chunks of 32.
__global__ void __launch_bounds__(256, 1) gemm_kernel(const float* __restrict__ A,
                                                      const float* __restrict__ bias,
                                                      float* __restrict__ out) {
    __shared__ __align__(16) unsigned char sAh[TILE_M * ROWB];
    __shared__ __align__(16) unsigned char sAl[TILE_M * ROWB];
    __shared__ __align__(16) unsigned char sWh[TILE_N * ROWB];
    __shared__ __align__(16) unsigned char sWl[TILE_N * ROWB];

    const int t    = threadIdx.x;
    const int wid  = t >> 5;
    const int lane = t & 31;
    const int wm   = wid & 1;     // 0..1 (64 rows each)
    const int wn   = wid >> 1;    // 0..3 (32 cols each)

    int bid = blockIdx.x;
    int seg, tstart, rstart, rend;
    if      (bid <  157) { seg = 0; tstart = 0;    rstart = 0;      rend =  20000; }
    else if (bid <  626) { seg = 1; tstart = 157;  rstart = 20000;  rend =  80000; }
    else if (bid < 1095) { seg = 2; tstart = 626;  rstart = 80000;  rend = 140000; }
    else if (bid < 1408) { seg = 3; tstart = 1095; rstart = 140000; rend = 180000; }
    else                 { seg = 4; tstart = 1408; rstart = 180000; rend = 200000; }
    const int row0 = rstart + (bid - tstart) * TILE_M;
    const int n0   = blockIdx.y * TILE_N;

    const uint32_t uAh = s2u(sAh), uAl = s2u(sAl), uWh = s2u(sWh), uWl = s2u(sWl);

    // staging mapping: row = t&127, half = t>>7 (16 floats each)
    const int srow = t & 127;
    const int half = t >> 7;
    int arow = row0 + srow;
    if (arow >= N_ATOMS) arow = N_ATOMS - 1;
    const float* wseg = g_Wt + (size_t)seg * OUT_F * KPAD + (size_t)(n0 + srow) * KPAD;
    const uint32_t stA = (uint32_t)srow * ROWB + (uint32_t)half * 32u;
    const uint32_t stW = stA;

    // fragment-load lane geometry
    const int aRow = wm * 64 + ((lane >> 3) & 1) * 8 + (lane & 7);
    const int aCh  = (lane >> 4) & 1;
    const int bRow = wn * 32 + (lane & 7);
    const int bCh  = (lane >> 3) & 1;

    float acc[4][4][4];
#pragma unroll
    for (int am = 0; am < 4; am++)
#pragma unroll
        for (int bn = 0; bn < 4; bn++)
#pragma unroll
            for (int e = 0; e < 4; e++) acc[am][bn][e] = 0.f;

    float4 va[4], vw[4];
    // prologue: load chunk 0
    {
        const float4* p = (const float4*)(A + (size_t)arow * IN_F + half * 16);
#pragma unroll
        for (int j = 0; j < 4; j++) va[j] = p[j];
        const float4* q = (const float4*)(wseg + half * 16);
#pragma unroll
        for (int j = 0; j < 4; j++) vw[j] = q[j];
    }

    for (int i = 0; i < NCHUNK; i++) {
        __syncthreads();   // smem free
        // ---- stage chunk i (split fp32 -> bf16 h/l, store) ----
        {
            uint32_t h[8], l[8];
#pragma unroll
            for (int j = 0; j < 4; j++) {
                split2(va[j].x, va[j].y, h[2*j],   l[2*j]);
                split2(va[j].z, va[j].w, h[2*j+1], l[2*j+1]);
            }
            sts128(uAh + stA,       h[0], h[1], h[2], h[3]);
            sts128(uAh + stA + 16u, h[4], h[5], h[6], h[7]);
            sts128(uAl + stA,       l[0], l[1], l[2], l[3]);
            sts128(uAl + stA + 16u, l[4], l[5], l[6], l[7]);
#pragma unroll
            for (int j = 0; j < 4; j++) {
                split2(vw[j].x, vw[j].y, h[2*j],   l[2*j]);
                split2(vw[j].z, vw[j].w, h[2*j+1], l[2*j+1]);
            }
            sts128(uWh + stW,       h[0], h[1], h[2], h[3]);
            sts128(uWh + stW + 16u, h[4], h[5], h[6], h[7]);
            sts128(uWl + stW,       l[0], l[1], l[2], l[3]);
            sts128(uWl + stW + 16u, l[4], l[5], l[6], l[7]);
        }
        __syncthreads();

        // ---- prefetch chunk i+1 into registers ----
        if (i + 1 < NCHUNK) {
            const int ii = i + 1;
            const int k0 = ii * KCH + half * 16;
            if (ii < 8) {
                const float4* p = (const float4*)(A + (size_t)arow * IN_F + k0);
#pragma unroll
                for (int j = 0; j < 4; j++) va[j] = p[j];
            } else if (ii < 16) {
                const float4* p = (const float4*)(g_G + (size_t)arow * GROW + (k0 - IN_F));
#pragma unroll
                for (int j = 0; j < 4; j++) va[j] = p[j];
            } else {
                if (half == 0) {
                    const float4* p = (const float4*)(g_G + (size_t)arow * GROW + 256);
                    va[0] = p[0]; va[1] = p[1];
                    va[2] = make_float4(0.f,0.f,0.f,0.f);
                    va[3] = make_float4(0.f,0.f,0.f,0.f);
                } else {
#pragma unroll
                    for (int j = 0; j < 4; j++) va[j] = make_float4(0.f,0.f,0.f,0.f);
                }
            }
            const float4* q = (const float4*)(wseg + ii * KCH + half * 16);
#pragma unroll
            for (int j = 0; j < 4; j++) vw[j] = q[j];
        }

        // ---- compute chunk i: 2 k16 steps x 3 terms x 16 mma ----
#pragma unroll
        for (int ks = 0; ks < 2; ks++) {
            uint32_t ah[4][4], al[4][4], bh[4][2], bl[4][2];
            const uint32_t ca = (uint32_t)(ks * 2 + aCh) * 16u;
            const uint32_t cb = (uint32_t)(ks * 2 + bCh) * 16u;
#pragma unroll
            for (int am = 0; am < 4; am++) {
                uint32_t off = (uint32_t)(aRow + am * 16) * ROWB + ca;
                ldmx4(ah[am], uAh + off);
                ldmx4(al[am], uAl + off);
            }
#pragma unroll
            for (int bn = 0; bn < 4; bn++) {
                uint32_t off = (uint32_t)(bRow + bn * 8) * ROWB + cb;
                ldmx2(bh[bn], uWh + off);
                ldmx2(bl[bn], uWl + off);
            }
#pragma unroll
            for (int am = 0; am < 4; am++)
#pragma unroll
                for (int bn = 0; bn < 4; bn++) {
                    mma_bf16(acc[am][bn], ah[am], bh[bn]);
                    mma_bf16(acc[am][bn], ah[am], bl[bn]);
                    mma_bf16(acc[am][bn], al[am], bh[bn]);
                }
        }
    }

    // ---- epilogue: bias + relu + store + BN column partial sums ----
    const int g   = lane >> 2;
    const int tig = lane & 3;
    float s_c[4][2], q_c[4][2];
#pragma unroll
    for (int bn = 0; bn < 4; bn++) { s_c[bn][0]=s_c[bn][1]=q_c[bn][0]=q_c[bn][1]=0.f; }

#pragma unroll
    for (int am = 0; am < 4; am++) {
        const int grow0 = row0 + wm * 64 + am * 16 + g;
        const int grow1 = grow0 + 8;
        const bool v0 = grow0 < rend;
        const bool v1 = grow1 < rend;
#pragma unroll
        for (int bn = 0; bn < 4; bn++) {
            const int col = n0 + wn * 32 + bn * 8 + 2 * tig;
            const float b0 = __ldg(&bias[col]);
            const float b1 = __ldg(&bias[col + 1]);
            float x0 = fmaxf(acc[am][bn][0] + b0, 0.f);
            float x1 = fmaxf(acc[am][bn][1] + b1, 0.f);
            float x2 = fmaxf(acc[am][bn][2] + b0, 0.f);
            float x3 = fmaxf(acc[am][bn][3] + b1, 0.f);
            if (!v0) { x0 = 0.f; x1 = 0.f; }
            if (!v1) { x2 = 0.f; x3 = 0.f; }
            if (v0) *(float2*)(out + (size_t)grow0 * OUT_F + col) = make_float2(x0, x1);
            if (v1) *(float2*)(out + (size_t)grow1 * OUT_F + col) = make_float2(x2, x3);
            s_c[bn][0] += x0 + x2;  s_c[bn][1] += x1 + x3;
            q_c[bn][0] += x0 * x0 + x2 * x2;
            q_c[bn][1] += x1 * x1 + x3 * x3;
        }
    }
#pragma unroll
    for (int bn = 0; bn < 4; bn++)
#pragma unroll
        for (int e = 0; e < 2; e++) {
            float s = s_c[bn][e], q = q_c[bn][e];
#pragma unroll
            for (int m = 4; m <= 16; m <<= 1) {
                s += __shfl_xor_sync(0xffffffffu, s, m);
                q += __shfl_xor_sync(0xffffffffu, q, m);
            }
            if (g == 0) {
                const int col = n0 + wn * 32 + bn * 8 + 2 * tig + e;
                atomicAdd(&g_sum[col], s);
                atomicAdd(&g_sumsq[col], q);
            }
        }
}

// ---------------- kernel 4: BN finalize (scale/shift per column) -------------
__global__ void bn_finalize_kernel(const float* __restrict__ bnw,
                                   const float* __restrict__ bnb) {
    int c = threadIdx.x;
    float mean = g_sum[c]   * (1.f / N_ATOMS);
    float var  = g_sumsq[c] * (1.f / N_ATOMS) - mean * mean;
    float sc   = bnw[c] / sqrtf(var + EPSV);
    g_scale[c] = sc;
    g_shift[c] = bnb[c] - mean * sc;
}

// ---------------- kernel 5: BN apply (vectorized, in place) ------------------
__global__ void bn_apply_kernel(float* __restrict__ out) {
    const int total4 = N_ATOMS * (OUT_F / 4);
    for (int i = blockIdx.x * blockDim.x + threadIdx.x; i < total4;
         i += gridDim.x * blockDim.x) {
        int c4 = i & 63;
        float4 v  = ((float4*)out)[i];
        float4 sc = ((const float4*)g_scale)[c4];
        float4 sh = ((const float4*)g_shift)[c4];
        v.x = v.x * sc.x + sh.x;
        v.y = v.y * sc.y + sh.y;
        v.z = v.z * sc.z + sh.z;
        v.w = v.w * sc.w + sh.w;
        ((float4*)out)[i] = v;
    }
}

// ---------------- launcher ---------------------------------------------------
extern "C" void kernel_launch(void* const* d_in, const int* in_sizes, int n_in,
                              void* d_out, int out_size) {
    const float* A = (const float*)d_in[0];
    const float* B = (const float*)d_in[1];
    const int *an[5], *bnp[5];
    if (in_sizes[3] == 20000) {      // interleaved (atom_d, bond_d) pairs
        for (int d = 0; d < 5; d++) {
            an[d]  = (const int*)d_in[2 + 2 * d];
            bnp[d] = (const int*)d_in[3 + 2 * d];
        }
    } else {                          // grouped
        for (int d = 0; d < 5; d++) {
            an[d]  = (const int*)d_in[2 + d];
            bnp[d] = (const int*)d_in[7 + d];
        }
    }
    const float* Wself = (const float*)d_in[12];
    const float* bias  = (const float*)d_in[13];
    const float* Wd[5];
    for (int d = 0; d < 5; d++) Wd[d] = (const float*)d_in[14 + d];
    const float* bnw = (const float*)d_in[19];
    const float* bnb = (const float*)d_in[20];
    float* out = (float*)d_out;

    prep_kernel<<<1024, 256>>>(Wself, Wd[0], Wd[1], Wd[2], Wd[3], Wd[4]);
    gather_kernel<<<N_ATOMS / 8, 256>>>(A, B,
        an[0], an[1], an[2], an[3], an[4],
        bnp[0], bnp[1], bnp[2], bnp[3], bnp[4]);
    gemm_kernel<<<dim3(1565, 2), 256>>>(A, bias, out);
    bn_finalize_kernel<<<1, 256>>>(bnw, bnb);
    bn_apply_kernel<<<2048, 256>>>(out);
}

// round 7
// speedup vs baseline: 1.2266x; 1.1174x over previous
#include <cuda_runtime.h>
#include <cuda_bf16.h>
#include <cstdint>

#define N_ATOMS 200000
#define IN_F    256
#define OUT_F   256
#define BOND_F  6
#define GROW2   288          // gathered row padded: 256 atom-sum + 6 bond + 26 pad
#define KPAD    544          // 256 + 288
#define KCH     32           // K per chunk
#define NCHUNK  17
#define TILE_M  128
#define TILE_N  128
#define EPSV    1e-5f

#define ROWB    80u          // smem bytes per row (64B data + 16B pad, conflict-free)
#define ABYTES  10240u       // 128 rows * 80B per operand-half
#define BUFB    40960u       // 4 operand-halves per buffer
#define SMEMB   81920u       // double buffered

// ---------------- device scratch (static: no allocations allowed) ------------
// all bf16 data stored as packed u32 pairs (lo=even k, hi=odd k)
__device__ uint32_t g_Ah[(size_t)N_ATOMS * 128];   // atom_features hi [N][256 bf16]
__device__ uint32_t g_Al[(size_t)N_ATOMS * 128];   // atom_features lo
__device__ uint32_t g_Gh[(size_t)N_ATOMS * 144];   // gathered hi [N][288 bf16]
__device__ uint32_t g_Gl[(size_t)N_ATOMS * 144];   // gathered lo
__device__ uint32_t g_Wh[5 * 256 * 272];           // weights hi [seg][n][544 bf16]
__device__ uint32_t g_Wl[5 * 256 * 272];           // weights lo
__device__ float g_sum[OUT_F];
__device__ float g_sumsq[OUT_F];
__device__ float g_scale[OUT_F];
__device__ float g_shift[OUT_F];

// ---------------- helpers ----------------------------------------------------
__device__ __forceinline__ uint32_t s2u(const void* p) {
    uint32_t a;
    asm("{ .reg .u64 t; cvta.to.shared.u64 t, %1; cvt.u32.u64 %0, t; }"
        : "=r"(a) : "l"(p));
    return a;
}
__device__ __forceinline__ void cpasync16(uint32_t s, const void* g) {
    asm volatile("cp.async.ca.shared.global [%0], [%1], 16;" :: "r"(s), "l"(g));
}
__device__ __forceinline__ void ldmx4(uint32_t* r, uint32_t addr) {
    asm volatile("ldmatrix.sync.aligned.m8n8.x4.shared.b16 {%0,%1,%2,%3}, [%4];"
                 : "=r"(r[0]), "=r"(r[1]), "=r"(r[2]), "=r"(r[3]) : "r"(addr));
}
// B operand: W stored [n][k] row-major == B^T -> NON-trans ldmatrix = col-major frag
__device__ __forceinline__ void ldmx2(uint32_t* r, uint32_t addr) {
    asm volatile("ldmatrix.sync.aligned.m8n8.x2.shared.b16 {%0,%1}, [%2];"
                 : "=r"(r[0]), "=r"(r[1]) : "r"(addr));
}
__device__ __forceinline__ void mma_bf16(float* c, const uint32_t* a, const uint32_t* b) {
    asm volatile(
        "mma.sync.aligned.m16n8k16.row.col.f32.bf16.bf16.f32 "
        "{%0,%1,%2,%3}, {%4,%5,%6,%7}, {%8,%9}, {%0,%1,%2,%3};"
        : "+f"(c[0]), "+f"(c[1]), "+f"(c[2]), "+f"(c[3])
        : "r"(a[0]), "r"(a[1]), "r"(a[2]), "r"(a[3]), "r"(b[0]), "r"(b[1]));
}
// split (x,y) into packed bf16 hi pair + lo pair
__device__ __forceinline__ void split2(float x, float y, uint32_t& h, uint32_t& l) {
    __nv_bfloat16 hx = __float2bfloat16(x);
    __nv_bfloat16 hy = __float2bfloat16(y);
    float rx = x - __bfloat162float(hx);
    float ry = y - __bfloat162float(hy);
    __nv_bfloat16 lx = __float2bfloat16(rx);
    __nv_bfloat16 ly = __float2bfloat16(ry);
    h = ((uint32_t)__bfloat16_as_ushort(hy) << 16) | __bfloat16_as_ushort(hx);
    l = ((uint32_t)__bfloat16_as_ushort(ly) << 16) | __bfloat16_as_ushort(lx);
}

// ---------------- kernel 1: split+transpose weights, zero BN accumulators ----
__global__ void prep_kernel(const float* __restrict__ Wself,
                            const float* __restrict__ W1, const float* __restrict__ W2,
                            const float* __restrict__ W3, const float* __restrict__ W4,
                            const float* __restrict__ W5) {
    int tid = blockIdx.x * blockDim.x + threadIdx.x;
    if (tid < OUT_F) { g_sum[tid] = 0.f; g_sumsq[tid] = 0.f; }
    const int total = 5 * 256 * 272;
    for (int i = tid; i < total; i += gridDim.x * blockDim.x) {
        int seg = i / (256 * 272);
        int rem = i - seg * (256 * 272);
        int n   = rem / 272;
        int kp  = rem - n * 272;
        const float* Wd = (seg == 0) ? W1 : (seg == 1) ? W2 : (seg == 2) ? W3
                        : (seg == 3) ? W4 : W5;
        float v[2];
#pragma unroll
        for (int e = 0; e < 2; e++) {
            int k = 2 * kp + e;
            if (k < IN_F)            v[e] = Wself[k * OUT_F + n];
            else if (k < IN_F + 262) v[e] = Wd[(k - IN_F) * OUT_F + n];
            else                     v[e] = 0.f;
        }
        uint32_t h, l;
        split2(v[0], v[1], h, l);
        g_Wh[i] = h;
        g_Wl[i] = l;
    }
}

// ---------------- kernel 1b: split atom_features to bf16 h/l -----------------
__global__ void splitA_kernel(const float* __restrict__ A) {
    const int n4 = N_ATOMS * 64;
    for (int i = blockIdx.x * blockDim.x + threadIdx.x; i < n4;
         i += gridDim.x * blockDim.x) {
        float4 v = ((const float4*)A)[i];
        uint32_t h0, l0, h1, l1;
        split2(v.x, v.y, h0, l0);
        split2(v.z, v.w, h1, l1);
        int row = i >> 6, c = i & 63;
        size_t o = (size_t)row * 128 + 2 * c;
        g_Ah[o] = h0; g_Ah[o + 1] = h1;
        g_Al[o] = l0; g_Al[o + 1] = l1;
    }
}

// ---------------- kernel 2: gather + neighbor sum -> bf16 h/l ---------------
__global__ void gather_kernel(const float* __restrict__ A, const float* __restrict__ B,
    const int* __restrict__ an1, const int* __restrict__ an2, const int* __restrict__ an3,
    const int* __restrict__ an4, const int* __restrict__ an5,
    const int* __restrict__ bn1, const int* __restrict__ bn2, const int* __restrict__ bn3,
    const int* __restrict__ bn4, const int* __restrict__ bn5) {
    int w    = (blockIdx.x * blockDim.x + threadIdx.x) >> 5;
    int lane = threadIdx.x & 31;
    if (w >= N_ATOMS) return;
    int deg, li; const int *an, *bnp;
    if      (w <  20000) { deg = 1; li = w;           an = an1; bnp = bn1; }
    else if (w <  80000) { deg = 2; li = w -  20000;  an = an2; bnp = bn2; }
    else if (w < 140000) { deg = 3; li = w -  80000;  an = an3; bnp = bn3; }
    else if (w < 180000) { deg = 4; li = w - 140000;  an = an4; bnp = bn4; }
    else                 { deg = 5; li = w - 180000;  an = an5; bnp = bn5; }

    float4 a0 = {0.f,0.f,0.f,0.f}, a1 = {0.f,0.f,0.f,0.f};
    float bacc = 0.f;
    for (int j = 0; j < deg; j++) {
        int ai = an[li * deg + j];
        const float4* src = (const float4*)(A + (size_t)ai * IN_F);
        float4 s0 = src[lane];
        float4 s1 = src[lane + 32];
        a0.x += s0.x; a0.y += s0.y; a0.z += s0.z; a0.w += s0.w;
        a1.x += s1.x; a1.y += s1.y; a1.z += s1.z; a1.w += s1.w;
        if (lane < BOND_F) {
            int bi = bnp[li * deg + j];
            bacc += B[(size_t)bi * BOND_F + lane];
        }
    }
    const size_t rb = (size_t)w * 144;
    uint32_t h0, l0, h1, l1;
    split2(a0.x, a0.y, h0, l0); split2(a0.z, a0.w, h1, l1);
    g_Gh[rb + 2 * lane] = h0; g_Gh[rb + 2 * lane + 1] = h1;
    g_Gl[rb + 2 * lane] = l0; g_Gl[rb + 2 * lane + 1] = l1;
    split2(a1.x, a1.y, h0, l0); split2(a1.z, a1.w, h1, l1);
    g_Gh[rb + 64 + 2 * lane] = h0; g_Gh[rb + 64 + 2 * lane + 1] = h1;
    g_Gl[rb + 64 + 2 * lane] = l0; g_Gl[rb + 64 + 2 * lane + 1] = l1;
    // bond part: cols 256..263 (u32 idx 128..131) + pad to 287 (idx 132..143)
    float bv = (lane < BOND_F) ? bacc : 0.f;
    float lo = __shfl_sync(0xffffffffu, bv, (2 * lane) & 31);
    float hi = __shfl_sync(0xffffffffu, bv, (2 * lane + 1) & 31);
    if (lane < 4) {
        split2(lo, hi, h0, l0);
        g_Gh[rb + 128 + lane] = h0;
        g_Gl[rb + 128 + lane] = l0;
    } else if (lane < 16) {
        g_Gh[rb + 128 + lane] = 0u;
        g_Gl[rb + 128 + lane] = 0u;
    }
}

// ---------------- kernel 3: bf16x3 mma.sync GEMM + bias + ReLU + BN stats ----
// CTA 256 thr = 8 warps (2M x 4N), tile 128x128, K=544 in 17 chunks of 32.
// cp.async double-buffered staging; pre-split bf16 operands; no in-loop ALU.
__global__ void __launch_bounds__(256) gemm_kernel(const float* __restrict__ bias,
                                                   float* __restrict__ out) {
    extern __shared__ __align__(16) unsigned char dynsmem[];
    const uint32_t base = s2u(dynsmem);

    const int t    = threadIdx.x;
    const int wid  = t >> 5;
    const int lane = t & 31;
    const int wm   = wid & 1;
    const int wn   = wid >> 1;

    int bid = blockIdx.x;
    int seg, tstart, rstart, rend;
    if      (bid <  157) { seg = 0; tstart = 0;    rstart = 0;      rend =  20000; }
    else if (bid <  626) { seg = 1; tstart = 157;  rstart = 20000;  rend =  80000; }
    else if (bid < 1095) { seg = 2; tstart = 626;  rstart = 80000;  rend = 140000; }
    else if (bid < 1408) { seg = 3; tstart = 1095; rstart = 140000; rend = 180000; }
    else                 { seg = 4; tstart = 1408; rstart = 180000; rend = 200000; }
    const int row0 = rstart + (bid - tstart) * TILE_M;
    const int n0   = blockIdx.y * TILE_N;

    // staging geometry: 2 units of 16B per thread per operand-half
    int srow[2], sc16[2];
    size_t aclamp[2];
    uint32_t wrowbase[2];
#pragma unroll
    for (int j = 0; j < 2; j++) {
        int u = t + j * 256;
        srow[j] = u >> 2;
        sc16[j] = u & 3;
        int ar = row0 + srow[j];
        if (ar >= N_ATOMS) ar = N_ATOMS - 1;
        aclamp[j] = (size_t)ar;
        wrowbase[j] = (uint32_t)(seg * 256 + n0 + srow[j]);
    }

    // fragment-load lane geometry
    const int aRow = wm * 64 + ((lane >> 3) & 1) * 8 + (lane & 7);
    const int aCh  = (lane >> 4) & 1;
    const int bRow = wn * 32 + (lane & 7);
    const int bCh  = (lane >> 3) & 1;

    float acc[4][4][4];
#pragma unroll
    for (int am = 0; am < 4; am++)
#pragma unroll
        for (int bn = 0; bn < 4; bn++)
#pragma unroll
            for (int e = 0; e < 4; e++) acc[am][bn][e] = 0.f;

#define STAGE(ii)                                                               \
    {                                                                           \
        const uint32_t bb = base + (uint32_t)((ii) & 1) * BUFB;                 \
        _Pragma("unroll")                                                       \
        for (int j = 0; j < 2; j++) {                                           \
            const uint32_t dst = bb + (uint32_t)srow[j] * ROWB                  \
                               + (uint32_t)sc16[j] * 16u;                       \
            const uint4 *pa_h, *pa_l;                                           \
            if ((ii) < 8) {                                                     \
                size_t o = aclamp[j] * 32 + (ii) * 4 + sc16[j];                 \
                pa_h = (const uint4*)g_Ah + o;                                  \
                pa_l = (const uint4*)g_Al + o;                                  \
            } else {                                                            \
                size_t o = aclamp[j] * 36 + ((ii) - 8) * 4 + sc16[j];           \
                pa_h = (const uint4*)g_Gh + o;                                  \
                pa_l = (const uint4*)g_Gl + o;                                  \
            }                                                                   \
            cpasync16(dst,               pa_h);                                 \
            cpasync16(dst + ABYTES,      pa_l);                                 \
            size_t wo = (size_t)wrowbase[j] * 68 + (ii) * 4 + sc16[j];          \
            cpasync16(dst + 2u * ABYTES, (const uint4*)g_Wh + wo);              \
            cpasync16(dst + 3u * ABYTES, (const uint4*)g_Wl + wo);              \
        }                                                                       \
        asm volatile("cp.async.commit_group;");                                 \
    }

    STAGE(0);

    for (int i = 0; i < NCHUNK; i++) {
        if (i + 1 < NCHUNK) {
            STAGE(i + 1);
            asm volatile("cp.async.wait_group 1;");
        } else {
            asm volatile("cp.async.wait_group 0;");
        }
        __syncthreads();

        const uint32_t bb  = base + (uint32_t)(i & 1) * BUFB;
        const uint32_t uAh = bb;
        const uint32_t uAl = bb + ABYTES;
        const uint32_t uWh = bb + 2u * ABYTES;
        const uint32_t uWl = bb + 3u * ABYTES;

#pragma unroll
        for (int ks = 0; ks < 2; ks++) {
            uint32_t ah[4][4], al[4][4], bh[4][2], bl[4][2];
            const uint32_t ca = (uint32_t)(ks * 2 + aCh) * 16u;
            const uint32_t cb = (uint32_t)(ks * 2 + bCh) * 16u;
#pragma unroll
            for (int am = 0; am < 4; am++) {
                uint32_t off = (uint32_t)(aRow + am * 16) * ROWB + ca;
                ldmx4(ah[am], uAh + off);
                ldmx4(al[am], uAl + off);
            }
#pragma unroll
            for (int bn = 0; bn < 4; bn++) {
                uint32_t off = (uint32_t)(bRow + bn * 8) * ROWB + cb;
                ldmx2(bh[bn], uWh + off);
                ldmx2(bl[bn], uWl + off);
            }
#pragma unroll
            for (int am = 0; am < 4; am++)
#pragma unroll
                for (int bn = 0; bn < 4; bn++) {
                    mma_bf16(acc[am][bn], ah[am], bh[bn]);
                    mma_bf16(acc[am][bn], ah[am], bl[bn]);
                    mma_bf16(acc[am][bn], al[am], bh[bn]);
                }
        }
        __syncthreads();
    }

    // ---- epilogue: bias + relu + store + BN column partial sums ----
    const int g   = lane >> 2;
    const int tig = lane & 3;
    float s_c[4][2], q_c[4][2];
#pragma unroll
    for (int bn = 0; bn < 4; bn++) { s_c[bn][0]=s_c[bn][1]=q_c[bn][0]=q_c[bn][1]=0.f; }

#pragma unroll
    for (int am = 0; am < 4; am++) {
        const int grow0 = row0 + wm * 64 + am * 16 + g;
        const int grow1 = grow0 + 8;
        const bool v0 = grow0 < rend;
        const bool v1 = grow1 < rend;
#pragma unroll
        for (int bn = 0; bn < 4; bn++) {
            const int col = n0 + wn * 32 + bn * 8 + 2 * tig;
            const float b0 = __ldg(&bias[col]);
            const float b1 = __ldg(&bias[col + 1]);
            float x0 = fmaxf(acc[am][bn][0] + b0, 0.f);
            float x1 = fmaxf(acc[am][bn][1] + b1, 0.f);
            float x2 = fmaxf(acc[am][bn][2] + b0, 0.f);
            float x3 = fmaxf(acc[am][bn][3] + b1, 0.f);
            if (!v0) { x0 = 0.f; x1 = 0.f; }
            if (!v1) { x2 = 0.f; x3 = 0.f; }
            if (v0) *(float2*)(out + (size_t)grow0 * OUT_F + col) = make_float2(x0, x1);
            if (v1) *(float2*)(out + (size_t)grow1 * OUT_F + col) = make_float2(x2, x3);
            s_c[bn][0] += x0 + x2;  s_c[bn][1] += x1 + x3;
            q_c[bn][0] += x0 * x0 + x2 * x2;
            q_c[bn][1] += x1 * x1 + x3 * x3;
        }
    }
#pragma unroll
    for (int bn = 0; bn < 4; bn++)
#pragma unroll
        for (int e = 0; e < 2; e++) {
            float s = s_c[bn][e], q = q_c[bn][e];
#pragma unroll
            for (int m = 4; m <= 16; m <<= 1) {
                s += __shfl_xor_sync(0xffffffffu, s, m);
                q += __shfl_xor_sync(0xffffffffu, q, m);
            }
            if (g == 0) {
                const int col = n0 + wn * 32 + bn * 8 + 2 * tig + e;
                atomicAdd(&g_sum[col], s);
                atomicAdd(&g_sumsq[col], q);
            }
        }
}

// ---------------- kernel 4: BN finalize (scale/shift per column) -------------
__global__ void bn_finalize_kernel(const float* __restrict__ bnw,
                                   const float* __restrict__ bnb) {
    int c = threadIdx.x;
    float mean = g_sum[c]   * (1.f / N_ATOMS);
    float var  = g_sumsq[c] * (1.f / N_ATOMS) - mean * mean;
    float sc   = bnw[c] / sqrtf(var + EPSV);
    g_scale[c] = sc;
    g_shift[c] = bnb[c] - mean * sc;
}

// ---------------- kernel 5: BN apply (vectorized, in place) ------------------
__global__ void bn_apply_kernel(float* __restrict__ out) {
    const int total4 = N_ATOMS * (OUT_F / 4);
    for (int i = blockIdx.x * blockDim.x + threadIdx.x; i < total4;
         i += gridDim.x * blockDim.x) {
        int c4 = i & 63;
        float4 v  = ((float4*)out)[i];
        float4 sc = ((const float4*)g_scale)[c4];
        float4 sh = ((const float4*)g_shift)[c4];
        v.x = v.x * sc.x + sh.x;
        v.y = v.y * sc.y + sh.y;
        v.z = v.z * sc.z + sh.z;
        v.w = v.w * sc.w + sh.w;
        ((float4*)out)[i] = v;
    }
}

// ---------------- launcher ---------------------------------------------------
extern "C" void kernel_launch(void* const* d_in, const int* in_sizes, int n_in,
                              void* d_out, int out_size) {
    const float* A = (const float*)d_in[0];
    const float* B = (const float*)d_in[1];
    const int *an[5], *bnp[5];
    if (in_sizes[3] == 20000) {      // interleaved (atom_d, bond_d) pairs
        for (int d = 0; d < 5; d++) {
            an[d]  = (const int*)d_in[2 + 2 * d];
            bnp[d] = (const int*)d_in[3 + 2 * d];
        }
    } else {                          // grouped
        for (int d = 0; d < 5; d++) {
            an[d]  = (const int*)d_in[2 + d];
            bnp[d] = (const int*)d_in[7 + d];
        }
    }
    const float* Wself = (const float*)d_in[12];
    const float* bias  = (const float*)d_in[13];
    const float* Wd[5];
    for (int d = 0; d < 5; d++) Wd[d] = (const float*)d_in[14 + d];
    const float* bnw = (const float*)d_in[19];
    const float* bnb = (const float*)d_in[20];
    float* out = (float*)d_out;

    cudaFuncSetAttribute(gemm_kernel,
                         cudaFuncAttributeMaxDynamicSharedMemorySize, SMEMB);

    prep_kernel<<<512, 256>>>(Wself, Wd[0], Wd[1], Wd[2], Wd[3], Wd[4]);
    splitA_kernel<<<4096, 256>>>(A);
    gather_kernel<<<N_ATOMS / 8, 256>>>(A, B,
        an[0], an[1], an[2], an[3], an[4],
        bnp[0], bnp[1], bnp[2], bnp[3], bnp[4]);
    gemm_kernel<<<dim3(1565, 2), 256, SMEMB>>>(bias, out);
    bn_finalize_kernel<<<1, 256>>>(bnw, bnb);
    bn_apply_kernel<<<2048, 256>>>(out);
}

// round 8
// speedup vs baseline: 1.6526x; 1.3474x over previous
#include <cuda_runtime.h>
#include <cuda_bf16.h>
#include <cstdint>

#define N_ATOMS 200000
#define IN_F    256
#define OUT_F   256
#define BOND_F  6
#define KCH     32           // K per chunk
#define NCHUNK  17
#define TILE_M  128
#define TILE_N  128
#define EPSV    1e-5f

#define ROWB    80u          // smem bytes per row (64B data + 16B pad, conflict-free)
#define ABYTES  10240u       // 128 rows * 80B per operand-half
#define BUFB    40960u       // 4 operand-halves per buffer
#define SMEMB   81920u       // double buffered

// ---------------- device scratch (static: no allocations allowed) ------------
// all bf16 data stored as packed u32 pairs (lo=even k, hi=odd k)
__device__ uint32_t g_Ah[(size_t)N_ATOMS * 128];   // atom_features hi [N][256 bf16]
__device__ uint32_t g_Al[(size_t)N_ATOMS * 128];   // atom_features lo
__device__ uint32_t g_Gh[(size_t)N_ATOMS * 144];   // gathered hi [N][288 bf16]
__device__ uint32_t g_Gl[(size_t)N_ATOMS * 144];   // gathered lo
__device__ uint32_t g_Wh[5 * 256 * 272];           // weights hi [seg][n][544 bf16]
__device__ uint32_t g_Wl[5 * 256 * 272];           // weights lo
__device__ float g_sum[OUT_F];
__device__ float g_sumsq[OUT_F];
__device__ float g_scale[OUT_F];
__device__ float g_shift[OUT_F];

// ---------------- helpers ----------------------------------------------------
__device__ __forceinline__ uint32_t s2u(const void* p) {
    uint32_t a;
    asm("{ .reg .u64 t; cvta.to.shared.u64 t, %1; cvt.u32.u64 %0, t; }"
        : "=r"(a) : "l"(p));
    return a;
}
__device__ __forceinline__ void cpasync16(uint32_t s, const void* g) {
    asm volatile("cp.async.ca.shared.global [%0], [%1], 16;" :: "r"(s), "l"(g));
}
__device__ __forceinline__ void ldmx4(uint32_t* r, uint32_t addr) {
    asm volatile("ldmatrix.sync.aligned.m8n8.x4.shared.b16 {%0,%1,%2,%3}, [%4];"
                 : "=r"(r[0]), "=r"(r[1]), "=r"(r[2]), "=r"(r[3]) : "r"(addr));
}
// B operand: W stored [n][k] row-major == B^T -> NON-trans ldmatrix = col-major frag
__device__ __forceinline__ void ldmx2(uint32_t* r, uint32_t addr) {
    asm volatile("ldmatrix.sync.aligned.m8n8.x2.shared.b16 {%0,%1}, [%2];"
                 : "=r"(r[0]), "=r"(r[1]) : "r"(addr));
}
__device__ __forceinline__ void mma_bf16(float* c, const uint32_t* a, const uint32_t* b) {
    asm volatile(
        "mma.sync.aligned.m16n8k16.row.col.f32.bf16.bf16.f32 "
        "{%0,%1,%2,%3}, {%4,%5,%6,%7}, {%8,%9}, {%0,%1,%2,%3};"
        : "+f"(c[0]), "+f"(c[1]), "+f"(c[2]), "+f"(c[3])
        : "r"(a[0]), "r"(a[1]), "r"(a[2]), "r"(a[3]), "r"(b[0]), "r"(b[1]));
}
// split (x,y) into packed bf16 hi pair + lo pair
__device__ __forceinline__ void split2(float x, float y, uint32_t& h, uint32_t& l) {
    __nv_bfloat16 hx = __float2bfloat16(x);
    __nv_bfloat16 hy = __float2bfloat16(y);
    float rx = x - __bfloat162float(hx);
    float ry = y - __bfloat162float(hy);
    __nv_bfloat16 lx = __float2bfloat16(rx);
    __nv_bfloat16 ly = __float2bfloat16(ry);
    h = ((uint32_t)__bfloat16_as_ushort(hy) << 16) | __bfloat16_as_ushort(hx);
    l = ((uint32_t)__bfloat16_as_ushort(ly) << 16) | __bfloat16_as_ushort(lx);
}

// ---------------- kernel 1: split+transpose weights, zero BN accumulators ----
__global__ void prep_kernel(const float* __restrict__ Wself,
                            const float* __restrict__ W1, const float* __restrict__ W2,
                            const float* __restrict__ W3, const float* __restrict__ W4,
                            const float* __restrict__ W5) {
    int tid = blockIdx.x * blockDim.x + threadIdx.x;
    if (tid < OUT_F) { g_sum[tid] = 0.f; g_sumsq[tid] = 0.f; }
    const int total = 5 * 256 * 272;
    for (int i = tid; i < total; i += gridDim.x * blockDim.x) {
        int seg = i / (256 * 272);
        int rem = i - seg * (256 * 272);
        int n   = rem / 272;
        int kp  = rem - n * 272;
        const float* Wd = (seg == 0) ? W1 : (seg == 1) ? W2 : (seg == 2) ? W3
                        : (seg == 3) ? W4 : W5;
        float v[2];
#pragma unroll
        for (int e = 0; e < 2; e++) {
            int k = 2 * kp + e;
            if (k < IN_F)            v[e] = Wself[k * OUT_F + n];
            else if (k < IN_F + 262) v[e] = Wd[(k - IN_F) * OUT_F + n];
            else                     v[e] = 0.f;
        }
        uint32_t h, l;
        split2(v[0], v[1], h, l);
        g_Wh[i] = h;
        g_Wl[i] = l;
    }
}

// ---------------- kernel 1b: split atom_features to bf16 h/l -----------------
__global__ void splitA_kernel(const float* __restrict__ A) {
    const int n4 = N_ATOMS * 64;
    for (int i = blockIdx.x * blockDim.x + threadIdx.x; i < n4;
         i += gridDim.x * blockDim.x) {
        float4 v = ((const float4*)A)[i];
        uint32_t h0, l0, h1, l1;
        split2(v.x, v.y, h0, l0);
        split2(v.z, v.w, h1, l1);
        int row = i >> 6, c = i & 63;
        size_t o = (size_t)row * 128 + 2 * c;
        g_Ah[o] = h0; g_Ah[o + 1] = h1;
        g_Al[o] = l0; g_Al[o + 1] = l1;
    }
}

// ---------------- kernel 2: gather + neighbor sum -> bf16 h/l ---------------
__global__ void gather_kernel(const float* __restrict__ A, const float* __restrict__ B,
    const int* __restrict__ an1, const int* __restrict__ an2, const int* __restrict__ an3,
    const int* __restrict__ an4, const int* __restrict__ an5,
    const int* __restrict__ bn1, const int* __restrict__ bn2, const int* __restrict__ bn3,
    const int* __restrict__ bn4, const int* __restrict__ bn5) {
    int w    = (blockIdx.x * blockDim.x + threadIdx.x) >> 5;
    int lane = threadIdx.x & 31;
    if (w >= N_ATOMS) return;
    int deg, li; const int *an, *bnp;
    if      (w <  20000) { deg = 1; li = w;           an = an1; bnp = bn1; }
    else if (w <  80000) { deg = 2; li = w -  20000;  an = an2; bnp = bn2; }
    else if (w < 140000) { deg = 3; li = w -  80000;  an = an3; bnp = bn3; }
    else if (w < 180000) { deg = 4; li = w - 140000;  an = an4; bnp = bn4; }
    else                 { deg = 5; li = w - 180000;  an = an5; bnp = bn5; }

    float4 a0 = {0.f,0.f,0.f,0.f}, a1 = {0.f,0.f,0.f,0.f};
    float bacc = 0.f;
    for (int j = 0; j < deg; j++) {
        int ai = an[li * deg + j];
        const float4* src = (const float4*)(A + (size_t)ai * IN_F);
        float4 s0 = src[lane];
        float4 s1 = src[lane + 32];
        a0.x += s0.x; a0.y += s0.y; a0.z += s0.z; a0.w += s0.w;
        a1.x += s1.x; a1.y += s1.y; a1.z += s1.z; a1.w += s1.w;
        if (lane < BOND_F) {
            int bi = bnp[li * deg + j];
            bacc += B[(size_t)bi * BOND_F + lane];
        }
    }
    const size_t rb = (size_t)w * 144;
    uint32_t h0, l0, h1, l1;
    split2(a0.x, a0.y, h0, l0); split2(a0.z, a0.w, h1, l1);
    g_Gh[rb + 2 * lane] = h0; g_Gh[rb + 2 * lane + 1] = h1;
    g_Gl[rb + 2 * lane] = l0; g_Gl[rb + 2 * lane + 1] = l1;
    split2(a1.x, a1.y, h0, l0); split2(a1.z, a1.w, h1, l1);
    g_Gh[rb + 64 + 2 * lane] = h0; g_Gh[rb + 64 + 2 * lane + 1] = h1;
    g_Gl[rb + 64 + 2 * lane] = l0; g_Gl[rb + 64 + 2 * lane + 1] = l1;
    // bond part: cols 256..263 (u32 idx 128..131) + pad to 287 (idx 132..143)
    float bv = (lane < BOND_F) ? bacc : 0.f;
    float lo = __shfl_sync(0xffffffffu, bv, (2 * lane) & 31);
    float hi = __shfl_sync(0xffffffffu, bv, (2 * lane + 1) & 31);
    if (lane < 4) {
        split2(lo, hi, h0, l0);
        g_Gh[rb + 128 + lane] = h0;
        g_Gl[rb + 128 + lane] = l0;
    } else if (lane < 16) {
        g_Gh[rb + 128 + lane] = 0u;
        g_Gl[rb + 128 + lane] = 0u;
    }
}

// ---------------- kernel 3: bf16x3 mma.sync GEMM + bias + ReLU + BN stats ----
// CTA 256 thr = 8 warps (2M x 4N), tile 128x128, K=544 in 17 chunks of 32.
// cp.async double-buffered staging; pre-split bf16 operands.
// Compute phase is TERM-MAJOR: 16 independent-accumulator MMAs per term, so
// no back-to-back RAW chains on the HMMA pipe.
__global__ void __launch_bounds__(256) gemm_kernel(const float* __restrict__ bias,
                                                   float* __restrict__ out) {
    extern __shared__ __align__(16) unsigned char dynsmem[];
    const uint32_t base = s2u(dynsmem);

    const int t    = threadIdx.x;
    const int wid  = t >> 5;
    const int lane = t & 31;
    const int wm   = wid & 1;
    const int wn   = wid >> 1;

    int bid = blockIdx.x;
    int seg, tstart, rstart, rend;
    if      (bid <  157) { seg = 0; tstart = 0;    rstart = 0;      rend =  20000; }
    else if (bid <  626) { seg = 1; tstart = 157;  rstart = 20000;  rend =  80000; }
    else if (bid < 1095) { seg = 2; tstart = 626;  rstart = 80000;  rend = 140000; }
    else if (bid < 1408) { seg = 3; tstart = 1095; rstart = 140000; rend = 180000; }
    else                 { seg = 4; tstart = 1408; rstart = 180000; rend = 200000; }
    const int row0 = rstart + (bid - tstart) * TILE_M;
    const int n0   = blockIdx.y * TILE_N;

    // staging geometry: 2 units of 16B per thread per operand-half
    int srow[2], sc16[2];
    size_t aclamp[2];
    uint32_t wrowbase[2];
#pragma unroll
    for (int j = 0; j < 2; j++) {
        int u = t + j * 256;
        srow[j] = u >> 2;
        sc16[j] = u & 3;
        int ar = row0 + srow[j];
        if (ar >= N_ATOMS) ar = N_ATOMS - 1;
        aclamp[j] = (size_t)ar;
        wrowbase[j] = (uint32_t)(seg * 256 + n0 + srow[j]);
    }

    // fragment-load lane geometry
    const int aRow = wm * 64 + ((lane >> 3) & 1) * 8 + (lane & 7);
    const int aCh  = (lane >> 4) & 1;
    const int bRow = wn * 32 + (lane & 7);
    const int bCh  = (lane >> 3) & 1;

    float acc[4][4][4];
#pragma unroll
    for (int am = 0; am < 4; am++)
#pragma unroll
        for (int bn = 0; bn < 4; bn++)
#pragma unroll
            for (int e = 0; e < 4; e++) acc[am][bn][e] = 0.f;

#define STAGE(ii)                                                               \
    {                                                                           \
        const uint32_t bb = base + (uint32_t)((ii) & 1) * BUFB;                 \
        _Pragma("unroll")                                                       \
        for (int j = 0; j < 2; j++) {                                           \
            const uint32_t dst = bb + (uint32_t)srow[j] * ROWB                  \
                               + (uint32_t)sc16[j] * 16u;                       \
            const uint4 *pa_h, *pa_l;                                           \
            if ((ii) < 8) {                                                     \
                size_t o = aclamp[j] * 32 + (ii) * 4 + sc16[j];                 \
                pa_h = (const uint4*)g_Ah + o;                                  \
                pa_l = (const uint4*)g_Al + o;                                  \
            } else {                                                            \
                size_t o = aclamp[j] * 36 + ((ii) - 8) * 4 + sc16[j];           \
                pa_h = (const uint4*)g_Gh + o;                                  \
                pa_l = (const uint4*)g_Gl + o;                                  \
            }                                                                   \
            cpasync16(dst,               pa_h);                                 \
            cpasync16(dst + ABYTES,      pa_l);                                 \
            size_t wo = (size_t)wrowbase[j] * 68 + (ii) * 4 + sc16[j];          \
            cpasync16(dst + 2u * ABYTES, (const uint4*)g_Wh + wo);              \
            cpasync16(dst + 3u * ABYTES, (const uint4*)g_Wl + wo);              \
        }                                                                       \
        asm volatile("cp.async.commit_group;");                                 \
    }

    STAGE(0);

    for (int i = 0; i < NCHUNK; i++) {
        if (i + 1 < NCHUNK) {
            STAGE(i + 1);
            asm volatile("cp.async.wait_group 1;");
        } else {
            asm volatile("cp.async.wait_group 0;");
        }
        __syncthreads();

        const uint32_t bb  = base + (uint32_t)(i & 1) * BUFB;
        const uint32_t uAh = bb;
        const uint32_t uAl = bb + ABYTES;
        const uint32_t uWh = bb + 2u * ABYTES;
        const uint32_t uWl = bb + 3u * ABYTES;

#pragma unroll
        for (int ks = 0; ks < 2; ks++) {
            uint32_t ah[4][4], al[4][4], bh[4][2], bl[4][2];
            const uint32_t ca = (uint32_t)(ks * 2 + aCh) * 16u;
            const uint32_t cb = (uint32_t)(ks * 2 + bCh) * 16u;
#pragma unroll
            for (int am = 0; am < 4; am++) {
                uint32_t off = (uint32_t)(aRow + am * 16) * ROWB + ca;
                ldmx4(ah[am], uAh + off);
                ldmx4(al[am], uAl + off);
            }
#pragma unroll
            for (int bn = 0; bn < 4; bn++) {
                uint32_t off = (uint32_t)(bRow + bn * 8) * ROWB + cb;
                ldmx2(bh[bn], uWh + off);
                ldmx2(bl[bn], uWl + off);
            }
            // term-major: 16 independent accumulators between reuses
#pragma unroll
            for (int am = 0; am < 4; am++)
#pragma unroll
                for (int bn = 0; bn < 4; bn++)
                    mma_bf16(acc[am][bn], ah[am], bh[bn]);
#pragma unroll
            for (int am = 0; am < 4; am++)
#pragma unroll
                for (int bn = 0; bn < 4; bn++)
                    mma_bf16(acc[am][bn], ah[am], bl[bn]);
#pragma unroll
            for (int am = 0; am < 4; am++)
#pragma unroll
                for (int bn = 0; bn < 4; bn++)
                    mma_bf16(acc[am][bn], al[am], bh[bn]);
        }
        __syncthreads();
    }

    // ---- epilogue: bias + relu + store + BN column partial sums ----
    const int g   = lane >> 2;
    const int tig = lane & 3;
    float s_c[4][2], q_c[4][2];
#pragma unroll
    for (int bn = 0; bn < 4; bn++) { s_c[bn][0]=s_c[bn][1]=q_c[bn][0]=q_c[bn][1]=0.f; }

#pragma unroll
    for (int am = 0; am < 4; am++) {
        const int grow0 = row0 + wm * 64 + am * 16 + g;
        const int grow1 = grow0 + 8;
        const bool v0 = grow0 < rend;
        const bool v1 = grow1 < rend;
#pragma unroll
        for (int bn = 0; bn < 4; bn++) {
            const int col = n0 + wn * 32 + bn * 8 + 2 * tig;
            const float b0 = __ldg(&bias[col]);
            const float b1 = __ldg(&bias[col + 1]);
            float x0 = fmaxf(acc[am][bn][0] + b0, 0.f);
            float x1 = fmaxf(acc[am][bn][1] + b1, 0.f);
            float x2 = fmaxf(acc[am][bn][2] + b0, 0.f);
            float x3 = fmaxf(acc[am][bn][3] + b1, 0.f);
            if (!v0) { x0 = 0.f; x1 = 0.f; }
            if (!v1) { x2 = 0.f; x3 = 0.f; }
            if (v0) *(float2*)(out + (size_t)grow0 * OUT_F + col) = make_float2(x0, x1);
            if (v1) *(float2*)(out + (size_t)grow1 * OUT_F + col) = make_float2(x2, x3);
            s_c[bn][0] += x0 + x2;  s_c[bn][1] += x1 + x3;
            q_c[bn][0] += x0 * x0 + x2 * x2;
            q_c[bn][1] += x1 * x1 + x3 * x3;
        }
    }
#pragma unroll
    for (int bn = 0; bn < 4; bn++)
#pragma unroll
        for (int e = 0; e < 2; e++) {
            float s = s_c[bn][e], q = q_c[bn][e];
#pragma unroll
            for (int m = 4; m <= 16; m <<= 1) {
                s += __shfl_xor_sync(0xffffffffu, s, m);
                q += __shfl_xor_sync(0xffffffffu, q, m);
            }
            if (g == 0) {
                const int col = n0 + wn * 32 + bn * 8 + 2 * tig + e;
                atomicAdd(&g_sum[col], s);
                atomicAdd(&g_sumsq[col], q);
            }
        }
}

// ---------------- kernel 4: BN finalize (scale/shift per column) -------------
__global__ void bn_finalize_kernel(const float* __restrict__ bnw,
                                   const float* __restrict__ bnb) {
    int c = threadIdx.x;
    float mean = g_sum[c]   * (1.f / N_ATOMS);
    float var  = g_sumsq[c] * (1.f / N_ATOMS) - mean * mean;
    float sc   = bnw[c] / sqrtf(var + EPSV);
    g_scale[c] = sc;
    g_shift[c] = bnb[c] - mean * sc;
}

// ---------------- kernel 5: BN apply (vectorized, in place) ------------------
__global__ void bn_apply_kernel(float* __restrict__ out) {
    const int total4 = N_ATOMS * (OUT_F / 4);
    for (int i = blockIdx.x * blockDim.x + threadIdx.x; i < total4;
         i += gridDim.x * blockDim.x) {
        int c4 = i & 63;
        float4 v  = ((float4*)out)[i];
        float4 sc = ((const float4*)g_scale)[c4];
        float4 sh = ((const float4*)g_shift)[c4];
        v.x = v.x * sc.x + sh.x;
        v.y = v.y * sc.y + sh.y;
        v.z = v.z * sc.z + sh.z;
        v.w = v.w * sc.w + sh.w;
        ((float4*)out)[i] = v;
    }
}

// ---------------- launcher ---------------------------------------------------
extern "C" void kernel_launch(void* const* d_in, const int* in_sizes, int n_in,
                              void* d_out, int out_size) {
    const float* A = (const float*)d_in[0];
    const float* B = (const float*)d_in[1];
    const int *an[5], *bnp[5];
    if (in_sizes[3] == 20000) {      // interleaved (atom_d, bond_d) pairs
        for (int d = 0; d < 5; d++) {
            an[d]  = (const int*)d_in[2 + 2 * d];
            bnp[d] = (const int*)d_in[3 + 2 * d];
        }
    } else {                          // grouped
        for (int d = 0; d < 5; d++) {
            an[d]  = (const int*)d_in[2 + d];
            bnp[d] = (const int*)d_in[7 + d];
        }
    }
    const float* Wself = (const float*)d_in[12];
    const float* bias  = (const float*)d_in[13];
    const float* Wd[5];
    for (int d = 0; d < 5; d++) Wd[d] = (const float*)d_in[14 + d];
    const float* bnw = (const float*)d_in[19];
    const float* bnb = (const float*)d_in[20];
    float* out = (float*)d_out;

    cudaFuncSetAttribute(gemm_kernel,
                         cudaFuncAttributeMaxDynamicSharedMemorySize, SMEMB);

    prep_kernel<<<512, 256>>>(Wself, Wd[0], Wd[1], Wd[2], Wd[3], Wd[4]);
    splitA_kernel<<<4096, 256>>>(A);
    gather_kernel<<<N_ATOMS / 8, 256>>>(A, B,
        an[0], an[1], an[2], an[3], an[4],
        bnp[0], bnp[1], bnp[2], bnp[3], bnp[4]);
    gemm_kernel<<<dim3(1565, 2), 256, SMEMB>>>(bias, out);
    bn_finalize_kernel<<<1, 256>>>(bnw, bnb);
    bn_apply_kernel<<<2048, 256>>>(out);
}